// round 14
// baseline (speedup 1.0000x reference)
#include <cuda_runtime.h>
#include <cstdint>

constexpr int OUT_ELEMS = 8192 * 512;

// Packed scratch (allocation-free device globals)
__device__ __align__(16) uint2    g_xpk[2ull * 2048 * 2048];   // q,k A-pack (split)
__device__ __align__(16) uint32_t g_xpkh[2048ull * 2048];      // v A-pack (hi)
__device__ __align__(16) uint2    g_wpk[2ull * 64 * 4096];     // Wq,Wk B-pack (split)
__device__ __align__(16) uint32_t g_wvhpk[64ull * 4096];       // Wv B-pack (hi)
__device__ __align__(16) uint32_t g_wohpk[64ull * 4096];       // Wo B-pack (hi)
__device__ __align__(16) uint2    g_qpk[64ull * 32 * 2048];    // qh A-pack per (b,h)
__device__ __align__(16) uint2    g_kpk[64ull * 16 * 4096];    // kh B-pack per (b,h)
__device__ __align__(16) float    g_q2[65536];
__device__ __align__(16) float    g_k2[65536];
__device__ __align__(16) float    g_vhf[8192ull * 512];
__device__ __align__(16) uint32_t g_vpkh[64ull * 32 * 2048];   // V^T B-pack (hi)
__device__ __align__(16) uint32_t g_atpkh[8192ull * 512];      // att A-pack (hi)

#define DEVI __device__ __forceinline__
DEVI uint32_t s2u(const void* p){uint32_t a;asm("{.reg .u64 t; cvta.to.shared.u64 t,%1; cvt.u32.u64 %0,t;}":"=r"(a):"l"(p));return a;}
DEVI uint32_t f2tf(float x){uint32_t r;asm("cvt.rna.tf32.f32 %0,%1;":"=r"(r):"f"(x));return r;}
DEVI uint2 split2(float x){uint32_t h=f2tf(x);return make_uint2(h,f2tf(x-__uint_as_float(h)));}
DEVI void cp16(uint32_t d,const void* s){asm volatile("cp.async.cg.shared.global [%0],[%1],16;"::"r"(d),"l"(s));}
#define CPC() asm volatile("cp.async.commit_group;":::"memory")
#define CPW() asm volatile("cp.async.wait_group 0;":::"memory")

DEVI void mma8(float* c,uint32_t a0,uint32_t a1,uint32_t a2,uint32_t a3,uint32_t b0,uint32_t b1){
    asm volatile("mma.sync.aligned.m16n8k8.row.col.f32.tf32.tf32.f32 "
        "{%0,%1,%2,%3},{%4,%5,%6,%7},{%8,%9},{%0,%1,%2,%3};"
        :"+f"(c[0]),"+f"(c[1]),"+f"(c[2]),"+f"(c[3])
        :"r"(a0),"r"(a1),"r"(a2),"r"(a3),"r"(b0),"r"(b1));
}

// Inverse index maps (verified R9-R11)
DEVI void inv_a(int p,int&r,int&c){
    int s0=p&1, l=(p>>1)&31, hf=(p>>6)&1, ks=(p>>7)&3, rb=p>>9;
    r=rb*16+s0*8+(l>>2); c=ks*8+hf*4+(l&3);
}
DEVI void inv_b(int p,int&k,int&n){
    int s=p&1, l=(p>>1)&31, ks=(p>>6)&3, nb=p>>8;
    n=nb*8+(l>>2); k=ks*8+(s<<2)+(l&3);
}
DEVI void inv_ah(int p,int&r,int&c){
    int s=p&3, l=(p>>2)&31, ks=(p>>7)&3, rb=p>>9;
    r=rb*16+(s&1)*8+(l>>2); c=ks*8+((s>>1)<<2)+(l&3);
}
// forward map into a 32-K hi A-pack chunk (inverse of inv_ah)
DEVI void sth(uint32_t* whi,int r,int c,float v){
    int rb=r>>4, ks=c>>3, l=((r&7)<<2)|(c&3), s=(((c>>2)&1)<<1)|((r>>3)&1);
    whi[((rb*4+ks)*32+l)*4+s]=f2tf(v);
}

// 3-pass split chunk, MI=2, pass-major — verified
template<int NJ>
DEVI void chunk_mma(const uint4* __restrict__ A4,const uint4* __restrict__ B4,
                    int wy,int wx,int lane,float acc[2][NJ][4]){
#pragma unroll
    for(int ks=0;ks<4;ks++){
        uint4 a[2][2], b[NJ];
#pragma unroll
        for(int mi=0;mi<2;mi++){
            const uint4* ap=A4+((wy*2+mi)*4+ks)*64+lane;
            a[mi][0]=ap[0]; a[mi][1]=ap[32];
        }
#pragma unroll
        for(int nj=0;nj<NJ;nj++) b[nj]=B4[((wx*NJ+nj)*4+ks)*32+lane];
#pragma unroll
        for(int mi=0;mi<2;mi++)
#pragma unroll
            for(int nj=0;nj<NJ;nj++)
                mma8(acc[mi][nj],a[mi][0].x,a[mi][0].z,a[mi][1].x,a[mi][1].z,b[nj].x,b[nj].z);
#pragma unroll
        for(int mi=0;mi<2;mi++)
#pragma unroll
            for(int nj=0;nj<NJ;nj++)
                mma8(acc[mi][nj],a[mi][0].y,a[mi][0].w,a[mi][1].y,a[mi][1].w,b[nj].x,b[nj].z);
#pragma unroll
        for(int mi=0;mi<2;mi++)
#pragma unroll
            for(int nj=0;nj<NJ;nj++)
                mma8(acc[mi][nj],a[mi][0].x,a[mi][0].z,a[mi][1].x,a[mi][1].z,b[nj].y,b[nj].w);
    }
}
// 1-pass hi chunk
template<int NJ>
DEVI void chunk_mma_hi(const uint4* __restrict__ A4,const uint2* __restrict__ B2,
                       int wy,int wx,int lane,float acc[2][NJ][4]){
#pragma unroll
    for(int ks=0;ks<4;ks++){
        uint4 a[2]; uint2 b[NJ];
#pragma unroll
        for(int mi=0;mi<2;mi++) a[mi]=A4[((wy*2+mi)*4+ks)*32+lane];
#pragma unroll
        for(int nj=0;nj<NJ;nj++) b[nj]=B2[((wx*NJ+nj)*4+ks)*32+lane];
#pragma unroll
        for(int mi=0;mi<2;mi++)
#pragma unroll
            for(int nj=0;nj<NJ;nj++)
                mma8(acc[mi][nj],a[mi].x,a[mi].y,a[mi].z,a[mi].w,b[nj].x,b[nj].y);
    }
}

template<int NJ,int STRIDE>
DEVI void acc2ep(float* ep,int wy,int wx,int lane,float acc[2][NJ][4]){
#pragma unroll
    for(int mi=0;mi<2;mi++)
#pragma unroll
        for(int nj=0;nj<NJ;nj++){
            int r=wy*32+(lane>>2)+mi*16, c=wx*(NJ*8)+nj*8+(lane&3)*2;
            ep[r*STRIDE+c]=acc[mi][nj][0];     ep[r*STRIDE+c+1]=acc[mi][nj][1];
            ep[(r+8)*STRIDE+c]=acc[mi][nj][2]; ep[(r+8)*STRIDE+c+1]=acc[mi][nj][3];
        }
}

// ------------------------- pack kernels (unchanged, verified) -------------------------
__global__ void pack_x(const float* __restrict__ q,const float* __restrict__ k){
    __shared__ float t[64][36];
    const float* src=blockIdx.z==0?q:k;
    const int m0=blockIdx.y, k0=blockIdx.x, tid=threadIdx.x;
#pragma unroll
    for(int i=0;i<2;i++){
        int r=(tid>>3)+i*32, c4=(tid&7)<<2;
        float4 x=*(const float4*)(src+(size_t)(m0*64+r)*512+k0*32+c4);
        t[r][c4]=x.x; t[r][c4+1]=x.y; t[r][c4+2]=x.z; t[r][c4+3]=x.w;
    }
    __syncthreads();
    uint2* dst=g_xpk+((size_t)(blockIdx.z*128+m0)*16+k0)*2048;
#pragma unroll
    for(int j=0;j<8;j+=2){
        int p=tid*8+j,r,c,r1,c1;
        inv_a(p,r,c); inv_a(p+1,r1,c1);
        uint2 w0=split2(t[r][c]), w1=split2(t[r1][c1]);
        *(uint4*)(dst+p)=make_uint4(w0.x,w0.y,w1.x,w1.y);
    }
}
__global__ void pack_xh(const float* __restrict__ v){
    __shared__ float t[64][36];
    const int m0=blockIdx.y, k0=blockIdx.x, tid=threadIdx.x;
#pragma unroll
    for(int i=0;i<2;i++){
        int r=(tid>>3)+i*32, c4=(tid&7)<<2;
        float4 x=*(const float4*)(v+(size_t)(m0*64+r)*512+k0*32+c4);
        t[r][c4]=x.x; t[r][c4+1]=x.y; t[r][c4+2]=x.z; t[r][c4+3]=x.w;
    }
    __syncthreads();
    uint32_t* dst=g_xpkh+((size_t)m0*16+k0)*2048;
#pragma unroll
    for(int j=0;j<8;j+=4){
        int p=tid*8+j; uint32_t w[4];
#pragma unroll
        for(int jj=0;jj<4;jj++){ int r,c; inv_ah(p+jj,r,c); w[jj]=f2tf(t[r][c]); }
        *(uint4*)(dst+p)=make_uint4(w[0],w[1],w[2],w[3]);
    }
}
__global__ void pack_w(const float* __restrict__ Wq,const float* __restrict__ Wk){
    __shared__ float t[32][132];
    const float* W=blockIdx.z==0?Wq:Wk;
    const int k0=blockIdx.x, n0=blockIdx.y, tid=threadIdx.x;
#pragma unroll
    for(int i=0;i<4;i++){
        int idx=tid+i*256, r=idx>>5, c4=(idx&31)<<2;
        float4 x=*(const float4*)(W+(size_t)(k0*32+r)*512+n0*128+c4);
        t[r][c4]=x.x; t[r][c4+1]=x.y; t[r][c4+2]=x.z; t[r][c4+3]=x.w;
    }
    __syncthreads();
    uint2* dst=g_wpk+((size_t)(blockIdx.z*4+n0)*16+k0)*4096;
#pragma unroll
    for(int j=0;j<16;j+=2){
        int p=tid*16+j,k,n,k1,n1;
        inv_b(p,k,n); inv_b(p+1,k1,n1);
        uint2 w0=split2(t[k][n]), w1=split2(t[k1][n1]);
        *(uint4*)(dst+p)=make_uint4(w0.x,w0.y,w1.x,w1.y);
    }
}
__global__ void pack_bh(const float* __restrict__ W, uint32_t* __restrict__ dpk){
    __shared__ float t[32][132];
    const int k0=blockIdx.x, n0=blockIdx.y, tid=threadIdx.x;
#pragma unroll
    for(int i=0;i<4;i++){
        int idx=tid+i*256, r=idx>>5, c4=(idx&31)<<2;
        float4 x=*(const float4*)(W+(size_t)(k0*32+r)*512+n0*128+c4);
        t[r][c4]=x.x; t[r][c4+1]=x.y; t[r][c4+2]=x.z; t[r][c4+3]=x.w;
    }
    __syncthreads();
    uint32_t* dst=dpk+((size_t)(n0*16+k0))*4096;
#pragma unroll
    for(int j=0;j<16;j+=2){
        int p=tid*16+j,k,n,k1,n1;
        inv_b(p,k,n); inv_b(p+1,k1,n1);
        *(uint2*)(dst+p)=make_uint2(f2tf(t[k][n]),f2tf(t[k1][n1]));
    }
}
__global__ void pack_vt(){
    __shared__ float t[32][68];
    const int c0=blockIdx.x, bh=blockIdx.y, b=bh>>3, h=bh&7, tid=threadIdx.x;
#pragma unroll
    for(int i=0;i<2;i++){
        int idx=tid+i*256, r=idx>>4, c4=(idx&15)<<2;
        float4 x=*(const float4*)(g_vhf+(size_t)(b*1024+c0*32+r)*512+h*64+c4);
        t[r][c4]=x.x; t[r][c4+1]=x.y; t[r][c4+2]=x.z; t[r][c4+3]=x.w;
    }
    __syncthreads();
    uint32_t* dst=g_vpkh+((size_t)bh*32+c0)*2048;
#pragma unroll
    for(int j=0;j<8;j+=2){
        int p=tid*8+j,k,n,k1,n1;
        inv_b(p,k,n); inv_b(p+1,k1,n1);
        *(uint2*)(dst+p)=make_uint2(f2tf(t[k][n]),f2tf(t[k1][n1]));
    }
}

// ------------------------- proj_qk (3-pass, 512 thr) — R11 verbatim -------------------------
__global__ __launch_bounds__(512,2) void proj_qk(){
    extern __shared__ __align__(16) char sm[];
    const int tid=threadIdx.x, lane=tid&31, warp=tid>>5, wy=warp>>3, wx=warp&7;
    const int bx=blockIdx.x, by=blockIdx.y, z=blockIdx.z;
    const uint32_t smb=s2u(sm);
    const uint4* Ag=(const uint4*)g_xpk+((size_t)(z*128+by)*16)*1024;
    const uint4* Bg=(const uint4*)g_wpk+((size_t)(z*4+bx)*16)*2048;
    float acc[2][2][4];
#pragma unroll
    for(int i=0;i<2;i++)
#pragma unroll
        for(int j=0;j<2;j++)
#pragma unroll
            for(int q2=0;q2<4;q2++) acc[i][j][q2]=0.f;
    auto stage=[&](int c,int bs){
        uint32_t Ad=smb+bs*49152, Bd=Ad+16384;
#pragma unroll
        for(int i=0;i<2;i++) cp16(Ad+(tid+i*512)*16, Ag+(size_t)c*1024+tid+i*512);
#pragma unroll
        for(int i=0;i<4;i++) cp16(Bd+(tid+i*512)*16, Bg+(size_t)c*2048+tid+i*512);
        CPC();
    };
    stage(0,0); CPW(); __syncthreads();
    for(int c=0;c<16;c++){
        if(c<15) stage(c+1,(c+1)&1);
        chunk_mma<2>((const uint4*)(sm+(c&1)*49152),(const uint4*)(sm+(c&1)*49152+16384),wy,wx,lane,acc);
        CPW(); __syncthreads();
    }
    float* ep=(float*)sm;
    acc2ep<2,132>(ep,wy,wx,lane,acc);
    __syncthreads();
    const int b=by>>4, t0=(by&15)*64, h0=bx*2;
    if(tid<128){
        int r=tid&63, hl=tid>>6;
        float s=0.f;
#pragma unroll
        for(int j=0;j<64;j++){float vv=ep[r*132+hl*64+j]; s=fmaf(vv,vv,s);}
        (z==0?g_q2:g_k2)[(size_t)(b*8+h0+hl)*1024+t0+r]=s;
    }
    if(z==0){
#pragma unroll
        for(int ch=0;ch<4;ch++){
            int hl=ch>>1, kk=ch&1;
            uint2* dst=g_qpk+(((size_t)(b*8+h0+hl)*16+(by&15))*2+kk)*2048;
#pragma unroll
            for(int j=0;j<4;j+=2){
                int p=tid*4+j,r,c,r1,c1;
                inv_a(p,r,c); inv_a(p+1,r1,c1);
                uint2 w0=split2(ep[r*132+hl*64+kk*32+c]);
                uint2 w1=split2(ep[r1*132+hl*64+kk*32+c1]);
                *(uint4*)(dst+p)=make_uint4(w0.x,w0.y,w1.x,w1.y);
            }
        }
    } else {
        const int n0=t0>>7, hs=(t0>>6)&1;
#pragma unroll
        for(int ch=0;ch<4;ch++){
            int hl=ch>>1, kk=ch&1;
            uint2* dst=g_kpk+(((size_t)(b*8+h0+hl)*8+n0)*2+kk)*4096+hs*2048;
#pragma unroll
            for(int j=0;j<4;j+=2){
                int p=tid*4+j,k,n,k1,n1;
                inv_b(p,k,n); inv_b(p+1,k1,n1);
                uint2 w0=split2(ep[n*132+hl*64+kk*32+k]);
                uint2 w1=split2(ep[n1*132+hl*64+kk*32+k1]);
                *(uint4*)(dst+p)=make_uint4(w0.x,w0.y,w1.x,w1.y);
            }
        }
    }
}

// ------------------------- proj_v (hi 1-pass) — R11 verbatim -------------------------
__global__ __launch_bounds__(256,4) void proj_v(){
    extern __shared__ __align__(16) char sm[];
    const int tid=threadIdx.x, lane=tid&31, warp=tid>>5, wy=warp>>2, wx=warp&3;
    const int bx=blockIdx.x, by=blockIdx.y;
    const uint32_t smb=s2u(sm);
    const uint4* Ag=(const uint4*)g_xpkh+((size_t)by*16)*512;
    const uint4* Bg=(const uint4*)g_wvhpk+((size_t)bx*16)*1024;
    float acc[2][4][4];
#pragma unroll
    for(int i=0;i<2;i++)
#pragma unroll
        for(int j=0;j<4;j++)
#pragma unroll
            for(int q2=0;q2<4;q2++) acc[i][j][q2]=0.f;
    auto stage=[&](int c,int bs){
        uint32_t Ad=smb+bs*8192, Bd=smb+16384+bs*16384;
#pragma unroll
        for(int i=0;i<2;i++) cp16(Ad+(tid+i*256)*16, Ag+(size_t)c*512+tid+i*256);
#pragma unroll
        for(int i=0;i<4;i++) cp16(Bd+(tid+i*256)*16, Bg+(size_t)c*1024+tid+i*256);
        CPC();
    };
    stage(0,0); CPW(); __syncthreads();
    for(int c=0;c<16;c++){
        if(c<15) stage(c+1,(c+1)&1);
        chunk_mma_hi<4>((const uint4*)(sm+(c&1)*8192),(const uint2*)(sm+16384+(c&1)*16384),wy,wx,lane,acc);
        CPW(); __syncthreads();
    }
    float* ep=(float*)sm;
    acc2ep<4,132>(ep,wy,wx,lane,acc);
    __syncthreads();
#pragma unroll
    for(int i=0;i<8;i++){
        int idx=tid+i*256, r=idx>>5, c4=(idx&31)<<2;
        *(float4*)(g_vhf+(size_t)(by*64+r)*512+bx*128+c4)=*(float4*)&ep[r*132+c4];
    }
}

// ------------------------- FUSED rbf+wv -------------------------
// grid (qt=16, bh=64), 512 thr. Per CTA: q rows qt*64..+63, loop 16 k-tiles of 64.
// smem: Aq 32KB@0 | Bk 2x32KB@32768 | V 2x16KB@98304 | Whi 16KB@131072 |
//       k2 4KB@147456 | q2 256B@151552   (total 151808)
__global__ __launch_bounds__(512,1) void rbfwv(float* __restrict__ wts){
    extern __shared__ __align__(16) char sm[];
    const int tid=threadIdx.x, lane=tid&31, warp=tid>>5, wy=warp>>3, wx=warp&7;
    const int qt=blockIdx.x, bh=blockIdx.y, b=bh>>3, h=bh&7;
    const uint32_t smb=s2u(sm);
    float* k2s=(float*)(sm+147456);
    float* q2s=(float*)(sm+151552);

    // stage persistent Aq (2 kd-chunks)
    const uint4* Aqg=(const uint4*)g_qpk+((size_t)(bh*16+qt)*2)*1024;
#pragma unroll
    for(int kk=0;kk<2;kk++)
#pragma unroll
        for(int i=0;i<2;i++)
            cp16(smb+kk*16384+(tid+i*512)*16, Aqg+(size_t)kk*1024+tid+i*512);

    auto stage=[&](int kt,int bs){
        uint32_t bkd=smb+32768+bs*32768;
#pragma unroll
        for(int kk=0;kk<2;kk++){
            const uint4* S=(const uint4*)(g_kpk+(((size_t)(bh*8+(kt>>1))*2+kk)*4096+(size_t)(kt&1)*2048));
#pragma unroll
            for(int i=0;i<2;i++) cp16(bkd+kk*16384+(tid+i*512)*16, S+tid+i*512);
        }
        uint32_t vd=smb+98304+bs*16384;
#pragma unroll
        for(int cc=0;cc<2;cc++){
            const uint4* S=(const uint4*)(g_vpkh+((size_t)bh*32+kt*2+cc)*2048);
            cp16(vd+cc*8192+tid*16, S+tid);
        }
        CPC();
    };
    stage(0,0);
    // norms while copies fly
    if(tid<64) q2s[tid]=g_q2[(size_t)bh*1024+qt*64+tid];
#pragma unroll
    for(int i=0;i<2;i++) k2s[tid+i*512]=g_k2[(size_t)bh*1024+tid+i*512];
    CPW(); __syncthreads();

    float acc2[2][1][4];
#pragma unroll
    for(int i=0;i<2;i++)
#pragma unroll
        for(int q2=0;q2<4;q2++) acc2[i][0][q2]=0.f;

    uint32_t* whi=(uint32_t*)(sm+131072);
    for(int kt=0;kt<16;kt++){
        const int cur=kt&1;
        if(kt<15) stage(kt+1,cur^1);
        // MMA1: S = Q K^T (3-pass), 2 kd-chunks
        float accS[2][1][4];
#pragma unroll
        for(int i=0;i<2;i++)
#pragma unroll
            for(int q2=0;q2<4;q2++) accS[i][0][q2]=0.f;
        chunk_mma<1>((const uint4*)sm,          (const uint4*)(sm+32768+cur*32768),      wy,wx,lane,accS);
        chunk_mma<1>((const uint4*)(sm+16384),  (const uint4*)(sm+32768+cur*32768+16384),wy,wx,lane,accS);
        // exp, gmem store, pack into Whi (smem)
        float* wb=wts+(((size_t)bh*1024+qt*64)*1024)+kt*64;
#pragma unroll
        for(int mi=0;mi<2;mi++){
            int r=wy*32+(lane>>2)+mi*16;
            int cb=wx*8+(lane&3)*2;
            float e00=__expf(2.f*accS[mi][0][0]-q2s[r]-k2s[kt*64+cb]);
            float e01=__expf(2.f*accS[mi][0][1]-q2s[r]-k2s[kt*64+cb+1]);
            float e10=__expf(2.f*accS[mi][0][2]-q2s[r+8]-k2s[kt*64+cb]);
            float e11=__expf(2.f*accS[mi][0][3]-q2s[r+8]-k2s[kt*64+cb+1]);
            *(float2*)(wb+(size_t)r*1024+cb)    =make_float2(e00,e01);
            *(float2*)(wb+(size_t)(r+8)*1024+cb)=make_float2(e10,e11);
            uint32_t* wc=whi+((cb>>5)<<11);
            int c5=cb&31;
            sth(wc,r,c5,e00);   sth(wc,r,c5+1,e01);
            sth(wc,r+8,c5,e10); sth(wc,r+8,c5+1,e11);
        }
        __syncthreads();   // Whi visible to all warps
        // MMA2: att += W @ V (hi 1-pass), 2 K-chunks of 32
        chunk_mma_hi<1>((const uint4*)(sm+131072),     (const uint2*)(sm+98304+cur*16384),     wy,wx,lane,acc2);
        chunk_mma_hi<1>((const uint4*)(sm+131072+8192),(const uint2*)(sm+98304+cur*16384+8192),wy,wx,lane,acc2);
        CPW(); __syncthreads();   // next tiles staged; all warps done with Whi/V
    }
    // att epilogue -> hi A-pack
    float* ep=(float*)sm;   // reuse Aq region
    acc2ep<1,68>(ep,wy,wx,lane,acc2);
    __syncthreads();
#pragma unroll
    for(int cc=0;cc<2;cc++){
        uint32_t* dst=g_atpkh+((size_t)(b*16+qt)*16+h*2+cc)*2048;
        uint32_t w[4];
#pragma unroll
        for(int jj=0;jj<4;jj++){ int r,cx; inv_ah(tid*4+jj,r,cx); w[jj]=f2tf(ep[r*68+cc*32+cx]); }
        *(uint4*)(dst+tid*4)=make_uint4(w[0],w[1],w[2],w[3]);
    }
}

// ------------------------- outproj (hi 1-pass) — R11 verbatim -------------------------
__global__ __launch_bounds__(256,4) void outproj_hi(float* __restrict__ out){
    extern __shared__ __align__(16) char sm[];
    const int tid=threadIdx.x, lane=tid&31, warp=tid>>5, wy=warp>>2, wx=warp&3;
    const int bx=blockIdx.x, by=blockIdx.y;
    const uint32_t smb=s2u(sm);
    const uint4* Ag=(const uint4*)g_atpkh+((size_t)by*16)*512;
    const uint4* Bg=(const uint4*)g_wohpk+((size_t)bx*16)*1024;
    float acc[2][4][4];
#pragma unroll
    for(int i=0;i<2;i++)
#pragma unroll
        for(int j=0;j<4;j++)
#pragma unroll
            for(int q2=0;q2<4;q2++) acc[i][j][q2]=0.f;
    auto stage=[&](int c,int bs){
        uint32_t Ad=smb+bs*8192, Bd=smb+16384+bs*16384;
#pragma unroll
        for(int i=0;i<2;i++) cp16(Ad+(tid+i*256)*16, Ag+(size_t)c*512+tid+i*256);
#pragma unroll
        for(int i=0;i<4;i++) cp16(Bd+(tid+i*256)*16, Bg+(size_t)c*1024+tid+i*256);
        CPC();
    };
    stage(0,0); CPW(); __syncthreads();
    for(int c=0;c<16;c++){
        if(c<15) stage(c+1,(c+1)&1);
        chunk_mma_hi<4>((const uint4*)(sm+(c&1)*8192),(const uint2*)(sm+16384+(c&1)*16384),wy,wx,lane,acc);
        CPW(); __syncthreads();
    }
    float* ep=(float*)sm;
    acc2ep<4,132>(ep,wy,wx,lane,acc);
    __syncthreads();
#pragma unroll
    for(int i=0;i<8;i++){
        int idx=tid+i*256, r=idx>>5, c4=(idx&31)<<2;
        *(float4*)(out+(size_t)(by*64+r)*512+bx*128+c4)=*(float4*)&ep[r*132+c4];
    }
}

// ---------------------------------------------------------------------------
extern "C" void kernel_launch(void* const* d_in,const int* in_sizes,int n_in,
                              void* d_out,int out_size){
    (void)in_sizes; (void)n_in; (void)out_size;
    const float* q =(const float*)d_in[0];
    const float* k =(const float*)d_in[1];
    const float* v =(const float*)d_in[2];
    const float* Wq=(const float*)d_in[3];
    const float* Wk=(const float*)d_in[4];
    const float* Wv=(const float*)d_in[5];
    const float* Wo=(const float*)d_in[6];
    float* out=(float*)d_out;
    float* wts=out+OUT_ELEMS;

    void* p;
    uint32_t *wvh,*woh;
    cudaGetSymbolAddress(&p,g_wvhpk); wvh=(uint32_t*)p;
    cudaGetSymbolAddress(&p,g_wohpk); woh=(uint32_t*)p;

    cudaFuncSetAttribute(proj_qk,    cudaFuncAttributeMaxDynamicSharedMemorySize, 98304);
    cudaFuncSetAttribute(proj_v,     cudaFuncAttributeMaxDynamicSharedMemorySize, 49152);
    cudaFuncSetAttribute(rbfwv,      cudaFuncAttributeMaxDynamicSharedMemorySize, 151808);
    cudaFuncSetAttribute(outproj_hi, cudaFuncAttributeMaxDynamicSharedMemorySize, 49152);

    pack_x<<<dim3(16,128,2),256>>>(q,k);
    pack_xh<<<dim3(16,128),256>>>(v);
    pack_w<<<dim3(16,4,2),256>>>(Wq,Wk);
    pack_bh<<<dim3(16,4),256>>>(Wv,wvh);
    pack_bh<<<dim3(16,4),256>>>(Wo,woh);
    proj_qk<<<dim3(4,128,2),512,98304>>>();
    proj_v<<<dim3(4,128),256,49152>>>();
    pack_vt<<<dim3(32,64),256>>>();
    rbfwv<<<dim3(16,64),512,151808>>>(wts);
    outproj_hi<<<dim3(4,128),256,49152>>>(out);
}

// round 15
// speedup vs baseline: 1.0908x; 1.0908x over previous
#include <cuda_runtime.h>
#include <cstdint>

constexpr int OUT_ELEMS = 8192 * 512;

// Packed scratch (allocation-free device globals)
__device__ __align__(16) uint2    g_xpk[2ull * 2048 * 2048];   // q,k A-pack (split)
__device__ __align__(16) uint32_t g_xpkh[2048ull * 2048];      // v A-pack (hi)
__device__ __align__(16) uint2    g_wpk[2ull * 64 * 4096];     // Wq,Wk B-pack (split)
__device__ __align__(16) uint32_t g_wvhpk[64ull * 4096];       // Wv B-pack (hi)
__device__ __align__(16) uint32_t g_wohpk[64ull * 4096];       // Wo B-pack (hi)
__device__ __align__(16) uint2    g_qpk[64ull * 32 * 2048];    // qh A-pack per (b,h)
__device__ __align__(16) uint2    g_kpk[64ull * 16 * 4096];    // kh B-pack per (b,h)
__device__ __align__(16) float    g_q2[65536];
__device__ __align__(16) float    g_k2[65536];
__device__ __align__(16) float    g_vhf[8192ull * 512];
__device__ __align__(16) uint32_t g_vpkh[64ull * 32 * 2048];   // V^T B-pack (hi)
__device__ __align__(16) uint32_t g_atpkh[8192ull * 512];      // att A-pack (hi)

#define DEVI __device__ __forceinline__
DEVI uint32_t s2u(const void* p){uint32_t a;asm("{.reg .u64 t; cvta.to.shared.u64 t,%1; cvt.u32.u64 %0,t;}":"=r"(a):"l"(p));return a;}
DEVI uint32_t f2tf(float x){uint32_t r;asm("cvt.rna.tf32.f32 %0,%1;":"=r"(r):"f"(x));return r;}
DEVI uint2 split2(float x){uint32_t h=f2tf(x);return make_uint2(h,f2tf(x-__uint_as_float(h)));}
DEVI void cp16(uint32_t d,const void* s){asm volatile("cp.async.cg.shared.global [%0],[%1],16;"::"r"(d),"l"(s));}
#define CPC() asm volatile("cp.async.commit_group;":::"memory")
#define CPW() asm volatile("cp.async.wait_group 0;":::"memory")

DEVI void mma8(float* c,uint32_t a0,uint32_t a1,uint32_t a2,uint32_t a3,uint32_t b0,uint32_t b1){
    asm volatile("mma.sync.aligned.m16n8k8.row.col.f32.tf32.tf32.f32 "
        "{%0,%1,%2,%3},{%4,%5,%6,%7},{%8,%9},{%0,%1,%2,%3};"
        :"+f"(c[0]),"+f"(c[1]),"+f"(c[2]),"+f"(c[3])
        :"r"(a0),"r"(a1),"r"(a2),"r"(a3),"r"(b0),"r"(b1));
}

// Inverse index maps (verified R9-R11)
DEVI void inv_a(int p,int&r,int&c){
    int s0=p&1, l=(p>>1)&31, hf=(p>>6)&1, ks=(p>>7)&3, rb=p>>9;
    r=rb*16+s0*8+(l>>2); c=ks*8+hf*4+(l&3);
}
DEVI void inv_b(int p,int&k,int&n){
    int s=p&1, l=(p>>1)&31, ks=(p>>6)&3, nb=p>>8;
    n=nb*8+(l>>2); k=ks*8+(s<<2)+(l&3);
}
DEVI void inv_ah(int p,int&r,int&c){
    int s=p&3, l=(p>>2)&31, ks=(p>>7)&3, rb=p>>9;
    r=rb*16+(s&1)*8+(l>>2); c=ks*8+((s>>1)<<2)+(l&3);
}

// 3-pass split chunk, MI=2, pass-major — verified
template<int NJ>
DEVI void chunk_mma(const uint4* __restrict__ A4,const uint4* __restrict__ B4,
                    int wy,int wx,int lane,float acc[2][NJ][4]){
#pragma unroll
    for(int ks=0;ks<4;ks++){
        uint4 a[2][2], b[NJ];
#pragma unroll
        for(int mi=0;mi<2;mi++){
            const uint4* ap=A4+((wy*2+mi)*4+ks)*64+lane;
            a[mi][0]=ap[0]; a[mi][1]=ap[32];
        }
#pragma unroll
        for(int nj=0;nj<NJ;nj++) b[nj]=B4[((wx*NJ+nj)*4+ks)*32+lane];
#pragma unroll
        for(int mi=0;mi<2;mi++)
#pragma unroll
            for(int nj=0;nj<NJ;nj++)
                mma8(acc[mi][nj],a[mi][0].x,a[mi][0].z,a[mi][1].x,a[mi][1].z,b[nj].x,b[nj].z);
#pragma unroll
        for(int mi=0;mi<2;mi++)
#pragma unroll
            for(int nj=0;nj<NJ;nj++)
                mma8(acc[mi][nj],a[mi][0].y,a[mi][0].w,a[mi][1].y,a[mi][1].w,b[nj].x,b[nj].z);
#pragma unroll
        for(int mi=0;mi<2;mi++)
#pragma unroll
            for(int nj=0;nj<NJ;nj++)
                mma8(acc[mi][nj],a[mi][0].x,a[mi][0].z,a[mi][1].x,a[mi][1].z,b[nj].y,b[nj].w);
    }
}
// 1-pass hi chunk
template<int NJ>
DEVI void chunk_mma_hi(const uint4* __restrict__ A4,const uint2* __restrict__ B2,
                       int wy,int wx,int lane,float acc[2][NJ][4]){
#pragma unroll
    for(int ks=0;ks<4;ks++){
        uint4 a[2]; uint2 b[NJ];
#pragma unroll
        for(int mi=0;mi<2;mi++) a[mi]=A4[((wy*2+mi)*4+ks)*32+lane];
#pragma unroll
        for(int nj=0;nj<NJ;nj++) b[nj]=B2[((wx*NJ+nj)*4+ks)*32+lane];
#pragma unroll
        for(int mi=0;mi<2;mi++)
#pragma unroll
            for(int nj=0;nj<NJ;nj++)
                mma8(acc[mi][nj],a[mi].x,a[mi].y,a[mi].z,a[mi].w,b[nj].x,b[nj].y);
    }
}

template<int NJ,int STRIDE>
DEVI void acc2ep(float* ep,int wy,int wx,int lane,float acc[2][NJ][4]){
#pragma unroll
    for(int mi=0;mi<2;mi++)
#pragma unroll
        for(int nj=0;nj<NJ;nj++){
            int r=wy*32+(lane>>2)+mi*16, c=wx*(NJ*8)+nj*8+(lane&3)*2;
            ep[r*STRIDE+c]=acc[mi][nj][0];     ep[r*STRIDE+c+1]=acc[mi][nj][1];
            ep[(r+8)*STRIDE+c]=acc[mi][nj][2]; ep[(r+8)*STRIDE+c+1]=acc[mi][nj][3];
        }
}

// ------------------------- pack kernels -------------------------
__global__ void pack_x(const float* __restrict__ q,const float* __restrict__ k){
    __shared__ float t[64][36];
    const float* src=blockIdx.z==0?q:k;
    const int m0=blockIdx.y, k0=blockIdx.x, tid=threadIdx.x;
#pragma unroll
    for(int i=0;i<2;i++){
        int r=(tid>>3)+i*32, c4=(tid&7)<<2;
        float4 x=*(const float4*)(src+(size_t)(m0*64+r)*512+k0*32+c4);
        t[r][c4]=x.x; t[r][c4+1]=x.y; t[r][c4+2]=x.z; t[r][c4+3]=x.w;
    }
    __syncthreads();
    uint2* dst=g_xpk+((size_t)(blockIdx.z*128+m0)*16+k0)*2048;
#pragma unroll
    for(int j=0;j<8;j+=2){
        int p=tid*8+j,r,c,r1,c1;
        inv_a(p,r,c); inv_a(p+1,r1,c1);
        uint2 w0=split2(t[r][c]), w1=split2(t[r1][c1]);
        *(uint4*)(dst+p)=make_uint4(w0.x,w0.y,w1.x,w1.y);
    }
}
__global__ void pack_xh(const float* __restrict__ v){
    __shared__ float t[64][36];
    const int m0=blockIdx.y, k0=blockIdx.x, tid=threadIdx.x;
#pragma unroll
    for(int i=0;i<2;i++){
        int r=(tid>>3)+i*32, c4=(tid&7)<<2;
        float4 x=*(const float4*)(v+(size_t)(m0*64+r)*512+k0*32+c4);
        t[r][c4]=x.x; t[r][c4+1]=x.y; t[r][c4+2]=x.z; t[r][c4+3]=x.w;
    }
    __syncthreads();
    uint32_t* dst=g_xpkh+((size_t)m0*16+k0)*2048;
#pragma unroll
    for(int j=0;j<8;j+=4){
        int p=tid*8+j; uint32_t w[4];
#pragma unroll
        for(int jj=0;jj<4;jj++){ int r,c; inv_ah(p+jj,r,c); w[jj]=f2tf(t[r][c]); }
        *(uint4*)(dst+p)=make_uint4(w[0],w[1],w[2],w[3]);
    }
}
__global__ void pack_w(const float* __restrict__ Wq,const float* __restrict__ Wk){
    __shared__ float t[32][132];
    const float* W=blockIdx.z==0?Wq:Wk;
    const int k0=blockIdx.x, n0=blockIdx.y, tid=threadIdx.x;
#pragma unroll
    for(int i=0;i<4;i++){
        int idx=tid+i*256, r=idx>>5, c4=(idx&31)<<2;
        float4 x=*(const float4*)(W+(size_t)(k0*32+r)*512+n0*128+c4);
        t[r][c4]=x.x; t[r][c4+1]=x.y; t[r][c4+2]=x.z; t[r][c4+3]=x.w;
    }
    __syncthreads();
    uint2* dst=g_wpk+((size_t)(blockIdx.z*4+n0)*16+k0)*4096;
#pragma unroll
    for(int j=0;j<16;j+=2){
        int p=tid*16+j,k,n,k1,n1;
        inv_b(p,k,n); inv_b(p+1,k1,n1);
        uint2 w0=split2(t[k][n]), w1=split2(t[k1][n1]);
        *(uint4*)(dst+p)=make_uint4(w0.x,w0.y,w1.x,w1.y);
    }
}
__global__ void pack_bh(const float* __restrict__ Wv,const float* __restrict__ Wo){
    __shared__ float t[32][132];
    const float* W=blockIdx.z==0?Wv:Wo;
    uint32_t* dpk=blockIdx.z==0?g_wvhpk:g_wohpk;
    const int k0=blockIdx.x, n0=blockIdx.y, tid=threadIdx.x;
#pragma unroll
    for(int i=0;i<4;i++){
        int idx=tid+i*256, r=idx>>5, c4=(idx&31)<<2;
        float4 x=*(const float4*)(W+(size_t)(k0*32+r)*512+n0*128+c4);
        t[r][c4]=x.x; t[r][c4+1]=x.y; t[r][c4+2]=x.z; t[r][c4+3]=x.w;
    }
    __syncthreads();
    uint32_t* dst=dpk+((size_t)(n0*16+k0))*4096;
#pragma unroll
    for(int j=0;j<16;j+=2){
        int p=tid*16+j,k,n,k1,n1;
        inv_b(p,k,n); inv_b(p+1,k1,n1);
        *(uint2*)(dst+p)=make_uint2(f2tf(t[k][n]),f2tf(t[k1][n1]));
    }
}
__global__ void pack_vt(){
    __shared__ float t[32][68];
    const int c0=blockIdx.x, bh=blockIdx.y, b=bh>>3, h=bh&7, tid=threadIdx.x;
#pragma unroll
    for(int i=0;i<2;i++){
        int idx=tid+i*256, r=idx>>4, c4=(idx&15)<<2;
        float4 x=*(const float4*)(g_vhf+(size_t)(b*1024+c0*32+r)*512+h*64+c4);
        t[r][c4]=x.x; t[r][c4+1]=x.y; t[r][c4+2]=x.z; t[r][c4+3]=x.w;
    }
    __syncthreads();
    uint32_t* dst=g_vpkh+((size_t)bh*32+c0)*2048;
#pragma unroll
    for(int j=0;j<8;j+=2){
        int p=tid*8+j,k,n,k1,n1;
        inv_b(p,k,n); inv_b(p+1,k1,n1);
        *(uint2*)(dst+p)=make_uint2(f2tf(t[k][n]),f2tf(t[k1][n1]));
    }
}

// ------------------------- proj_qk: 256 thr, NJ=4 (R10-verified shape) -------------------------
__global__ __launch_bounds__(256,2) void proj_qk(){
    extern __shared__ __align__(16) char sm[];
    const int tid=threadIdx.x, lane=tid&31, warp=tid>>5, wy=warp>>2, wx=warp&3;
    const int bx=blockIdx.x, by=blockIdx.y, z=blockIdx.z;
    const uint32_t smb=s2u(sm);
    const uint4* Ag=(const uint4*)g_xpk+((size_t)(z*128+by)*16)*1024;
    const uint4* Bg=(const uint4*)g_wpk+((size_t)(z*4+bx)*16)*2048;
    float acc[2][4][4];
#pragma unroll
    for(int i=0;i<2;i++)
#pragma unroll
        for(int j=0;j<4;j++)
#pragma unroll
            for(int q2=0;q2<4;q2++) acc[i][j][q2]=0.f;
    auto stage=[&](int c,int bs){
        uint32_t Ad=smb+bs*49152, Bd=Ad+16384;
#pragma unroll
        for(int i=0;i<4;i++) cp16(Ad+(tid+i*256)*16, Ag+(size_t)c*1024+tid+i*256);
#pragma unroll
        for(int i=0;i<8;i++) cp16(Bd+(tid+i*256)*16, Bg+(size_t)c*2048+tid+i*256);
        CPC();
    };
    stage(0,0); CPW(); __syncthreads();
    for(int c=0;c<16;c++){
        if(c<15) stage(c+1,(c+1)&1);
        chunk_mma<4>((const uint4*)(sm+(c&1)*49152),(const uint4*)(sm+(c&1)*49152+16384),wy,wx,lane,acc);
        CPW(); __syncthreads();
    }
    float* ep=(float*)sm;
    acc2ep<4,132>(ep,wy,wx,lane,acc);
    __syncthreads();
    const int b=by>>4, t0=(by&15)*64, h0=bx*2;
    if(tid<128){
        int r=tid&63, hl=tid>>6;
        float s=0.f;
#pragma unroll
        for(int j=0;j<64;j++){float vv=ep[r*132+hl*64+j]; s=fmaf(vv,vv,s);}
        (z==0?g_q2:g_k2)[(size_t)(b*8+h0+hl)*1024+t0+r]=s;
    }
    if(z==0){
#pragma unroll
        for(int ch=0;ch<4;ch++){
            int hl=ch>>1, kk=ch&1;
            uint2* dst=g_qpk+(((size_t)(b*8+h0+hl)*16+(by&15))*2+kk)*2048;
#pragma unroll
            for(int j=0;j<8;j+=2){
                int p=tid*8+j,r,c,r1,c1;
                inv_a(p,r,c); inv_a(p+1,r1,c1);
                uint2 w0=split2(ep[r*132+hl*64+kk*32+c]);
                uint2 w1=split2(ep[r1*132+hl*64+kk*32+c1]);
                *(uint4*)(dst+p)=make_uint4(w0.x,w0.y,w1.x,w1.y);
            }
        }
    } else {
        const int n0=t0>>7, hs=(t0>>6)&1;
#pragma unroll
        for(int ch=0;ch<4;ch++){
            int hl=ch>>1, kk=ch&1;
            uint2* dst=g_kpk+(((size_t)(b*8+h0+hl)*8+n0)*2+kk)*4096+hs*2048;
#pragma unroll
            for(int j=0;j<8;j+=2){
                int p=tid*8+j,k,n,k1,n1;
                inv_b(p,k,n); inv_b(p+1,k1,n1);
                uint2 w0=split2(ep[n*132+hl*64+kk*32+k]);
                uint2 w1=split2(ep[n1*132+hl*64+kk*32+k1]);
                *(uint4*)(dst+p)=make_uint4(w0.x,w0.y,w1.x,w1.y);
            }
        }
    }
}

// ------------------------- proj_v (hi 1-pass) — R11 verbatim -------------------------
__global__ __launch_bounds__(256,4) void proj_v(){
    extern __shared__ __align__(16) char sm[];
    const int tid=threadIdx.x, lane=tid&31, warp=tid>>5, wy=warp>>2, wx=warp&3;
    const int bx=blockIdx.x, by=blockIdx.y;
    const uint32_t smb=s2u(sm);
    const uint4* Ag=(const uint4*)g_xpkh+((size_t)by*16)*512;
    const uint4* Bg=(const uint4*)g_wvhpk+((size_t)bx*16)*1024;
    float acc[2][4][4];
#pragma unroll
    for(int i=0;i<2;i++)
#pragma unroll
        for(int j=0;j<4;j++)
#pragma unroll
            for(int q2=0;q2<4;q2++) acc[i][j][q2]=0.f;
    auto stage=[&](int c,int bs){
        uint32_t Ad=smb+bs*8192, Bd=smb+16384+bs*16384;
#pragma unroll
        for(int i=0;i<2;i++) cp16(Ad+(tid+i*256)*16, Ag+(size_t)c*512+tid+i*256);
#pragma unroll
        for(int i=0;i<4;i++) cp16(Bd+(tid+i*256)*16, Bg+(size_t)c*1024+tid+i*256);
        CPC();
    };
    stage(0,0); CPW(); __syncthreads();
    for(int c=0;c<16;c++){
        if(c<15) stage(c+1,(c+1)&1);
        chunk_mma_hi<4>((const uint4*)(sm+(c&1)*8192),(const uint2*)(sm+16384+(c&1)*16384),wy,wx,lane,acc);
        CPW(); __syncthreads();
    }
    float* ep=(float*)sm;
    acc2ep<4,132>(ep,wy,wx,lane,acc);
    __syncthreads();
#pragma unroll
    for(int i=0;i<8;i++){
        int idx=tid+i*256, r=idx>>5, c4=(idx&31)<<2;
        *(float4*)(g_vhf+(size_t)(by*64+r)*512+bx*128+c4)=*(float4*)&ep[r*132+c4];
    }
}

// ------------------------- rbf (3-pass, 512 thr) — R11 verbatim -------------------------
__global__ __launch_bounds__(512,2) void rbf_tc(float* __restrict__ wts){
    extern __shared__ __align__(16) char sm[];
    const int tid=threadIdx.x, lane=tid&31, warp=tid>>5, wy=warp>>3, wx=warp&7;
    const int kt=blockIdx.x, qt=blockIdx.y, bh=blockIdx.z;
    const uint32_t smb=s2u(sm);
    float* q2s=(float*)(sm+98304); float* k2s=q2s+64;
    const uint4* Ag=(const uint4*)g_qpk+((size_t)(bh*16+qt)*2)*1024;
    const uint4* Bg=(const uint4*)g_kpk+((size_t)(bh*8+kt)*2)*2048;
#pragma unroll
    for(int kk=0;kk<2;kk++){
#pragma unroll
        for(int i=0;i<2;i++) cp16(smb+kk*16384+(tid+i*512)*16, Ag+(size_t)kk*1024+tid+i*512);
#pragma unroll
        for(int i=0;i<4;i++) cp16(smb+32768+kk*32768+(tid+i*512)*16, Bg+(size_t)kk*2048+tid+i*512);
    }
    CPC();
    if(tid<64) q2s[tid]=g_q2[(size_t)bh*1024+qt*64+tid];
    else if(tid<192) k2s[tid-64]=g_k2[(size_t)bh*1024+kt*128+tid-64];
    CPW(); __syncthreads();
    float acc[2][2][4];
#pragma unroll
    for(int i=0;i<2;i++)
#pragma unroll
        for(int j=0;j<2;j++)
#pragma unroll
            for(int q2=0;q2<4;q2++) acc[i][j][q2]=0.f;
    chunk_mma<2>((const uint4*)sm,(const uint4*)(sm+32768),wy,wx,lane,acc);
    chunk_mma<2>((const uint4*)(sm+16384),(const uint4*)(sm+65536),wy,wx,lane,acc);
#pragma unroll
    for(int mi=0;mi<2;mi++)
#pragma unroll
        for(int nj=0;nj<2;nj++){
            int r=wy*32+(lane>>2)+mi*16, c=wx*16+nj*8+(lane&3)*2;
            acc[mi][nj][0]=__expf(2.f*acc[mi][nj][0]-q2s[r]-k2s[c]);
            acc[mi][nj][1]=__expf(2.f*acc[mi][nj][1]-q2s[r]-k2s[c+1]);
            acc[mi][nj][2]=__expf(2.f*acc[mi][nj][2]-q2s[r+8]-k2s[c]);
            acc[mi][nj][3]=__expf(2.f*acc[mi][nj][3]-q2s[r+8]-k2s[c+1]);
        }
    __syncthreads();
    float* ep=(float*)sm;
    acc2ep<2,132>(ep,wy,wx,lane,acc);
    __syncthreads();
    float* wb=wts+((size_t)bh*1024+qt*64)*1024+kt*128;
#pragma unroll
    for(int i=0;i<4;i++){
        int idx=tid+i*512, r=idx>>5, c4=(idx&31)<<2;
        *(float4*)(wb+(size_t)r*1024+c4)=*(float4*)&ep[r*132+c4];
    }
}

// ------------------------- wv: att = W @ V, hi 1-pass — R11 verbatim -------------------------
__global__ __launch_bounds__(256,4) void wv_hi(const float* __restrict__ wts){
    extern __shared__ __align__(16) char sm[];
    const int tid=threadIdx.x, lane=tid&31, warp=tid>>5, wy=warp>>2, wx=warp&3;
    const int qt=blockIdx.x, bh=blockIdx.y;
    const uint32_t smb=s2u(sm);
    const float* wb=wts+((size_t)bh*1024+qt*64)*1024;
    const uint4* Bg=(const uint4*)g_vpkh+(size_t)bh*32*512;
    float acc[2][2][4];
#pragma unroll
    for(int i=0;i<2;i++)
#pragma unroll
        for(int j=0;j<2;j++)
#pragma unroll
            for(int q2=0;q2<4;q2++) acc[i][j][q2]=0.f;
    auto stage=[&](int c,int bs){
        uint32_t fd=smb+32768+bs*9216, bd=smb+16384+bs*8192;
#pragma unroll
        for(int i=0;i<2;i++){
            int idx=tid+i*256, r=idx>>3, c4=(idx&7)<<2;
            cp16(fd+(r*36+c4)*4, wb+(size_t)r*1024+c*32+c4);
            cp16(bd+idx*16, Bg+(size_t)c*512+idx);
        }
        CPC();
    };
    auto cvtA=[&](int bs){
        const float* stg=(const float*)(sm+32768+bs*9216);
        uint32_t* dst=(uint32_t*)(sm+bs*8192);
#pragma unroll
        for(int j=0;j<8;j+=4){
            int p=tid*8+j; uint32_t w[4];
#pragma unroll
            for(int jj=0;jj<4;jj++){ int r,cc; inv_ah(p+jj,r,cc); w[jj]=f2tf(stg[r*36+cc]); }
            *(uint4*)(dst+p)=make_uint4(w[0],w[1],w[2],w[3]);
        }
    };
    stage(0,0); CPW(); __syncthreads(); cvtA(0); __syncthreads();
    for(int c=0;c<32;c++){
        if(c<31) stage(c+1,(c+1)&1);
        chunk_mma_hi<2>((const uint4*)(sm+(c&1)*8192),(const uint2*)(sm+16384+(c&1)*8192),wy,wx,lane,acc);
        CPW(); __syncthreads();
        if(c<31) cvtA((c+1)&1);
        __syncthreads();
    }
    float* ep=(float*)sm;
    acc2ep<2,68>(ep,wy,wx,lane,acc);
    __syncthreads();
    const int b=bh>>3, h=bh&7;
#pragma unroll
    for(int cc=0;cc<2;cc++){
        uint32_t* dst=g_atpkh+((size_t)(b*16+qt)*16+h*2+cc)*2048;
#pragma unroll
        for(int j=0;j<8;j+=4){
            int p=tid*8+j; uint32_t w[4];
#pragma unroll
            for(int jj=0;jj<4;jj++){ int r,ccx; inv_ah(p+jj,r,ccx); w[jj]=f2tf(ep[r*68+cc*32+ccx]); }
            *(uint4*)(dst+p)=make_uint4(w[0],w[1],w[2],w[3]);
        }
    }
}

// ------------------------- outproj (hi 1-pass) — R11 verbatim -------------------------
__global__ __launch_bounds__(256,4) void outproj_hi(float* __restrict__ out){
    extern __shared__ __align__(16) char sm[];
    const int tid=threadIdx.x, lane=tid&31, warp=tid>>5, wy=warp>>2, wx=warp&3;
    const int bx=blockIdx.x, by=blockIdx.y;
    const uint32_t smb=s2u(sm);
    const uint4* Ag=(const uint4*)g_atpkh+((size_t)by*16)*512;
    const uint4* Bg=(const uint4*)g_wohpk+((size_t)bx*16)*1024;
    float acc[2][4][4];
#pragma unroll
    for(int i=0;i<2;i++)
#pragma unroll
        for(int j=0;j<4;j++)
#pragma unroll
            for(int q2=0;q2<4;q2++) acc[i][j][q2]=0.f;
    auto stage=[&](int c,int bs){
        uint32_t Ad=smb+bs*8192, Bd=smb+16384+bs*16384;
#pragma unroll
        for(int i=0;i<2;i++) cp16(Ad+(tid+i*256)*16, Ag+(size_t)c*512+tid+i*256);
#pragma unroll
        for(int i=0;i<4;i++) cp16(Bd+(tid+i*256)*16, Bg+(size_t)c*1024+tid+i*256);
        CPC();
    };
    stage(0,0); CPW(); __syncthreads();
    for(int c=0;c<16;c++){
        if(c<15) stage(c+1,(c+1)&1);
        chunk_mma_hi<4>((const uint4*)(sm+(c&1)*8192),(const uint2*)(sm+16384+(c&1)*16384),wy,wx,lane,acc);
        CPW(); __syncthreads();
    }
    float* ep=(float*)sm;
    acc2ep<4,132>(ep,wy,wx,lane,acc);
    __syncthreads();
#pragma unroll
    for(int i=0;i<8;i++){
        int idx=tid+i*256, r=idx>>5, c4=(idx&31)<<2;
        *(float4*)(out+(size_t)(by*64+r)*512+bx*128+c4)=*(float4*)&ep[r*132+c4];
    }
}

// ---------------------------------------------------------------------------
extern "C" void kernel_launch(void* const* d_in,const int* in_sizes,int n_in,
                              void* d_out,int out_size){
    (void)in_sizes; (void)n_in; (void)out_size;
    const float* q =(const float*)d_in[0];
    const float* k =(const float*)d_in[1];
    const float* v =(const float*)d_in[2];
    const float* Wq=(const float*)d_in[3];
    const float* Wk=(const float*)d_in[4];
    const float* Wv=(const float*)d_in[5];
    const float* Wo=(const float*)d_in[6];
    float* out=(float*)d_out;
    float* wts=out+OUT_ELEMS;

    cudaFuncSetAttribute(proj_qk,    cudaFuncAttributeMaxDynamicSharedMemorySize, 98304);
    cudaFuncSetAttribute(proj_v,     cudaFuncAttributeMaxDynamicSharedMemorySize, 49152);
    cudaFuncSetAttribute(rbf_tc,     cudaFuncAttributeMaxDynamicSharedMemorySize, 99072);
    cudaFuncSetAttribute(wv_hi,      cudaFuncAttributeMaxDynamicSharedMemorySize, 51200);
    cudaFuncSetAttribute(outproj_hi, cudaFuncAttributeMaxDynamicSharedMemorySize, 49152);

    pack_x<<<dim3(16,128,2),256>>>(q,k);
    pack_xh<<<dim3(16,128),256>>>(v);
    pack_w<<<dim3(16,4,2),256>>>(Wq,Wk);
    pack_bh<<<dim3(16,4,2),256>>>(Wv,Wo);
    proj_qk<<<dim3(4,128,2),256,98304>>>();
    proj_v<<<dim3(4,128),256,49152>>>();
    pack_vt<<<dim3(32,64),256>>>();
    rbf_tc<<<dim3(8,16,64),512,99072>>>(wts);
    wv_hi<<<dim3(16,64),256,51200>>>(wts);
    outproj_hi<<<dim3(4,128),256,49152>>>(out);
}